// round 10
// baseline (speedup 1.0000x reference)
#include <cuda_runtime.h>
#include <cuda_fp16.h>

// SSIM loss, single fused kernel, fp16 datapath with CENTERED fields.
// u' = p+t-1 (zero-mean), v = p-t. Conv fields X=(u',v), Y=(u'^2,v^2) as
// half2 -> all fp16-accumulated quantities are O(0.1): no cancellation.
// Weights sum to 1: A=A'+1, C=C'+2A'+1, recovered exactly in fp32 epilogue.
// R10: Y staged in its own smem array (computed once per pixel in the halo
// phase) -> h-pass does 2x LDS.32 per tap and ZERO muls, moving ~8K HMUL2
// per block off the binding fma pipe onto the half-idle LSU.
// smem padded to 58KB: forces <=3 blocks/SM (blocks slow 4-block regime).

#define TW    32
#define TH    64
#define HALO  5
#define EW    42
#define EH    74
#define XP    43              // pitch (half2) input tiles
#define HP    33              // pitch (8B rec) h-pass array

#define IMG_H 512
#define IMG_W 512
#define N_PLANES 96
#define GX    16
#define GY    8
#define NBLK  (GX*GY*N_PLANES)   // 12288
#define N_PIX 25165824.0

#define SX_OFF   0
#define SY_OFF   (EH*XP*4)             // 12728
#define HQ_OFF   (SY_OFF + EH*XP*4)    // 25456
#define RED_OFF  (HQ_OFF + EH*HP*8)    // 44992
#define SMEM_TOTAL 59392               // 58KB: forces <=3 blocks/SM

__device__ constexpr float GW[11] = {
    0.00102838f, 0.00759877f, 0.03600077f, 0.10936071f, 0.21300553f,
    0.26601175f,
    0.21300553f, 0.10936071f, 0.03600077f, 0.00759877f, 0.00102838f
};

struct __align__(8) HQrec { __half2 ab; __half2 cd; };

__device__ float g_part[NBLK];
__device__ unsigned int g_count;

__global__ __launch_bounds__(512, 3)
void ssim_tile_kernel(const float* __restrict__ pred,
                      const float* __restrict__ targ,
                      float* __restrict__ out)
{
    extern __shared__ char smem[];
    __half2 (*sX)[XP] = (__half2(*)[XP])(smem + SX_OFF);
    __half2 (*sY)[XP] = (__half2(*)[XP])(smem + SY_OFF);
    HQrec   (*hQ)[HP] = (HQrec(*)[HP])(smem + HQ_OFF);
    float* red    = (float*)(smem + RED_OFF);
    int* lastflag = (int*)(smem + RED_OFF + 16*4);

    const int tid = threadIdx.x;
    const int ty0 = blockIdx.y * TH;
    const int tx0 = blockIdx.x * TW;
    const size_t pbase = (size_t)blockIdx.z * (IMG_H * IMG_W);

    // ---- load halo tile: centered (u', v) and its square, both half2 ----
    #pragma unroll
    for (int it = 0; it < 7; it++) {
        int idx = tid + it * 512;
        if (idx < EH * EW) {
            int r = idx / EW;
            int c = idx - r * EW;
            int gy = ty0 + r - HALO;
            int gx = tx0 + c - HALO;
            bool ok = ((unsigned)gy < (unsigned)IMG_H) & ((unsigned)gx < (unsigned)IMG_W);
            float a = 0.f, b = 0.f;
            if (ok) {
                size_t off = pbase + (size_t)gy * IMG_W + gx;
                a = pred[off];
                b = targ[off];
            }
            __half2 X = __floats2half2_rn(a + b - 1.0f, a - b);
            sX[r][c] = X;
            sY[r][c] = __hmul2(X, X);
        }
    }
    __syncthreads();

    // ---- horizontal pass: 74 rows x 8 quad-groups = 592 items ----
    #pragma unroll
    for (int it = 0; it < 2; it++) {
        int g = tid + it * 512;
        if (g < EH * (TW / 4)) {
            const int r  = g >> 3;
            const int c0 = (g & 7) * 4;
            __half2 aX[4], aY[4];
            #pragma unroll
            for (int j = 0; j < 4; j++) {
                aX[j] = __floats2half2_rn(0.f, 0.f);
                aY[j] = aX[j];
            }

            #pragma unroll
            for (int i = 0; i < 14; i++) {
                __half2 X = sX[r][c0 + i];
                __half2 Y = sY[r][c0 + i];
                #pragma unroll
                for (int j = 0; j < 4; j++) {
                    int k = i - j;
                    if (k >= 0 && k <= 10) {
                        __half2 w2 = __float2half2_rn(GW[k]);
                        aX[j] = __hfma2(X, w2, aX[j]);
                        aY[j] = __hfma2(Y, w2, aY[j]);
                    }
                }
            }
            #pragma unroll
            for (int j = 0; j < 4; j++) {
                HQrec q; q.ab = aX[j]; q.cd = aY[j];
                hQ[r][c0 + j] = q;      // one STS.64
            }
        }
    }
    __syncthreads();

    // ---- vertical pass + SSIM: thread -> (x, 4 adjacent y) ----
    const int x  = tid & 31;
    const int y0 = (tid >> 5) * 4;     // 0..60

    __half2 vX[4], vY[4];
    #pragma unroll
    for (int j = 0; j < 4; j++) {
        vX[j] = __floats2half2_rn(0.f, 0.f);
        vY[j] = vX[j];
    }

    #pragma unroll
    for (int i = 0; i < 14; i++) {
        HQrec q = hQ[y0 + i][x];       // one LDS.64 per tap
        #pragma unroll
        for (int j = 0; j < 4; j++) {
            int k = i - j;
            if (k >= 0 && k <= 10) {
                __half2 w2 = __float2half2_rn(GW[k]);
                vX[j] = __hfma2(q.ab, w2, vX[j]);
                vY[j] = __hfma2(q.cd, w2, vY[j]);
            }
        }
    }

    float lsum = 0.f;
    const float C1 = 1e-4f;
    const float C2 = 9e-4f;
    #pragma unroll
    for (int j = 0; j < 4; j++) {
        float Ap = __low2float(vX[j]);    // A' = A - 1
        float B  = __high2float(vX[j]);
        float Cp = __low2float(vY[j]);    // C' = C - 2A' - 1
        float Dv = __high2float(vY[j]);
        float A2 = fmaf(Ap, Ap + 2.0f, 1.0f);   // A^2
        float B2 = B * B;
        float t2m12 = (A2 - B2) * 0.5f;
        float msum  = (A2 + B2) * 0.5f;
        float e = Ap + 0.5f;                    // (C-D)/2 = (C'-D)/2 + A' + .5
        float t2s12 = (Cp - Dv) * 0.5f + e - t2m12;
        float ssum  = (Cp + Dv) * 0.5f + e - msum;
        float num = (t2m12 + C1) * (t2s12 + C2);
        float den = (msum + C1) * (ssum + C2) + 1e-8f;
        lsum += __fdividef(num, den);
    }

    // ---- block reduce, unique partial slot ----
    #pragma unroll
    for (int o = 16; o; o >>= 1)
        lsum += __shfl_xor_sync(0xffffffffu, lsum, o);
    if ((tid & 31) == 0) red[tid >> 5] = lsum;
    __syncthreads();

    if (tid == 0) {
        float s = 0.f;
        #pragma unroll
        for (int w = 0; w < 16; w++) s += red[w];
        int bid = (blockIdx.z * GY + blockIdx.y) * GX + blockIdx.x;
        g_part[bid] = s;
        __threadfence();
        unsigned int prev = atomicAdd(&g_count, 1u);
        *lastflag = (prev == NBLK - 1) ? 1 : 0;
    }
    __syncthreads();

    // ---- last block: final reduction over all partials ----
    if (*lastflag) {
        __threadfence();
        const float4* p4 = (const float4*)g_part;
        float s = 0.f;
        #pragma unroll
        for (int it = 0; it < 6; it++) {
            float4 v = p4[tid + it * 512];
            s += (v.x + v.y) + (v.z + v.w);
        }
        #pragma unroll
        for (int o = 16; o; o >>= 1)
            s += __shfl_xor_sync(0xffffffffu, s, o);
        if ((tid & 31) == 0) red[tid >> 5] = s;
        __syncthreads();
        if (tid == 0) {
            float t = 0.f;
            #pragma unroll
            for (int w = 0; w < 16; w++) t += red[w];
            out[0] = (float)(1.0 - (double)t * (1.0 / N_PIX));
            g_count = 0;   // self-reset for next graph replay
        }
    }
}

extern "C" void kernel_launch(void* const* d_in, const int* in_sizes, int n_in,
                              void* d_out, int out_size)
{
    const float* pred = (const float*)d_in[0];
    const float* targ = (const float*)d_in[1];

    cudaFuncSetAttribute(ssim_tile_kernel,
                         cudaFuncAttributeMaxDynamicSharedMemorySize, SMEM_TOTAL);
    dim3 grid(GX, GY, N_PLANES);   // 16 x 8 x 96
    ssim_tile_kernel<<<grid, 512, SMEM_TOTAL>>>(pred, targ, (float*)d_out);
}

// round 11
// speedup vs baseline: 1.1520x; 1.1520x over previous
#include <cuda_runtime.h>
#include <cuda_fp16.h>

// SSIM loss, single fused kernel, fp16 datapath with CENTERED fields.
// u' = p+t-1 (zero-mean), v = p-t. Conv fields X=(u',v), Y=(u'^2,v^2) as
// half2 -> all fp16-accumulated quantities are O(0.1): no cancellation.
// Weights sum to 1: A=A'+1, C=C'+2A'+1, recovered exactly in fp32 epilogue.
// R11: 32x128 tile (halo 5): halo amp 1.41, h-pass row amp 1.078, half the
// blocks -> fixed overheads amortized. v-pass = 2 sequential rounds of 4
// rows (unroll 1) to hold register pressure at the proven ~40.
// Y computed in h-pass via HMUL2 (R10's staged-Y variant measured slower).

#define TW    32
#define TH    128
#define HALO  5
#define EW    42
#define EH    138
#define XP    43              // pitch (half2) input tile
#define HP    33              // pitch (8B rec) h-pass array

#define IMG_H 512
#define IMG_W 512
#define N_PLANES 96
#define GX    16
#define GY    4
#define NBLK  (GX*GY*N_PLANES)   // 6144
#define N_PIX 25165824.0

#define SX_OFF   0
#define HQ_OFF   (EH*XP*4)             // 23736
#define RED_OFF  (HQ_OFF + EH*HP*8)    // 60168
#define SMEM_TOTAL (RED_OFF + 16*4 + 16)   // 60248 -> 3 blocks/SM naturally

__device__ constexpr float GW[11] = {
    0.00102838f, 0.00759877f, 0.03600077f, 0.10936071f, 0.21300553f,
    0.26601175f,
    0.21300553f, 0.10936071f, 0.03600077f, 0.00759877f, 0.00102838f
};

struct __align__(8) HQrec { __half2 ab; __half2 cd; };

__device__ float g_part[NBLK];
__device__ unsigned int g_count;

__global__ __launch_bounds__(512, 3)
void ssim_tile_kernel(const float* __restrict__ pred,
                      const float* __restrict__ targ,
                      float* __restrict__ out)
{
    extern __shared__ char smem[];
    __half2 (*sX)[XP] = (__half2(*)[XP])(smem + SX_OFF);
    HQrec   (*hQ)[HP] = (HQrec(*)[HP])(smem + HQ_OFF);
    float* red    = (float*)(smem + RED_OFF);
    int* lastflag = (int*)(smem + RED_OFF + 16*4);

    const int tid = threadIdx.x;
    const int ty0 = blockIdx.y * TH;
    const int tx0 = blockIdx.x * TW;
    const size_t pbase = (size_t)blockIdx.z * (IMG_H * IMG_W);

    // ---- load halo tile, compute centered (u', v), store half2 ----
    #pragma unroll
    for (int it = 0; it < 12; it++) {
        int idx = tid + it * 512;
        if (idx < EH * EW) {
            int r = idx / EW;
            int c = idx - r * EW;
            int gy = ty0 + r - HALO;
            int gx = tx0 + c - HALO;
            bool ok = ((unsigned)gy < (unsigned)IMG_H) & ((unsigned)gx < (unsigned)IMG_W);
            float a = 0.f, b = 0.f;
            if (ok) {
                size_t off = pbase + (size_t)gy * IMG_W + gx;
                a = pred[off];
                b = targ[off];
            }
            sX[r][c] = __floats2half2_rn(a + b - 1.0f, a - b);
        }
    }
    __syncthreads();

    // ---- horizontal pass: 138 rows x 8 quad-groups = 1104 items ----
    #pragma unroll
    for (int it = 0; it < 3; it++) {
        int g = tid + it * 512;
        if (g < EH * (TW / 4)) {
            const int r  = g >> 3;
            const int c0 = (g & 7) * 4;
            __half2 aX[4], aY[4];
            #pragma unroll
            for (int j = 0; j < 4; j++) {
                aX[j] = __floats2half2_rn(0.f, 0.f);
                aY[j] = aX[j];
            }

            #pragma unroll
            for (int i = 0; i < 14; i++) {
                __half2 X = sX[r][c0 + i];
                __half2 Y = __hmul2(X, X);
                #pragma unroll
                for (int j = 0; j < 4; j++) {
                    int k = i - j;
                    if (k >= 0 && k <= 10) {
                        __half2 w2 = __float2half2_rn(GW[k]);
                        aX[j] = __hfma2(X, w2, aX[j]);
                        aY[j] = __hfma2(Y, w2, aY[j]);
                    }
                }
            }
            #pragma unroll
            for (int j = 0; j < 4; j++) {
                HQrec q; q.ab = aX[j]; q.cd = aY[j];
                hQ[r][c0 + j] = q;      // one STS.64
            }
        }
    }
    __syncthreads();

    // ---- vertical pass + SSIM: thread -> (x, 8 rows as 2 rounds of 4) ----
    const int x   = tid & 31;
    const int yb  = (tid >> 5) * 8;    // 0..120

    float lsum = 0.f;
    const float C1 = 1e-4f;
    const float C2 = 9e-4f;

    #pragma unroll 1
    for (int rd = 0; rd < 2; rd++) {
        const int y0 = yb + rd * 4;

        __half2 vX[4], vY[4];
        #pragma unroll
        for (int j = 0; j < 4; j++) {
            vX[j] = __floats2half2_rn(0.f, 0.f);
            vY[j] = vX[j];
        }

        #pragma unroll
        for (int i = 0; i < 14; i++) {
            HQrec q = hQ[y0 + i][x];   // one LDS.64 per tap
            #pragma unroll
            for (int j = 0; j < 4; j++) {
                int k = i - j;
                if (k >= 0 && k <= 10) {
                    __half2 w2 = __float2half2_rn(GW[k]);
                    vX[j] = __hfma2(q.ab, w2, vX[j]);
                    vY[j] = __hfma2(q.cd, w2, vY[j]);
                }
            }
        }

        #pragma unroll
        for (int j = 0; j < 4; j++) {
            float Ap = __low2float(vX[j]);    // A' = A - 1
            float B  = __high2float(vX[j]);
            float Cp = __low2float(vY[j]);    // C' = C - 2A' - 1
            float Dv = __high2float(vY[j]);
            float A2 = fmaf(Ap, Ap + 2.0f, 1.0f);   // A^2
            float B2 = B * B;
            float t2m12 = (A2 - B2) * 0.5f;
            float msum  = (A2 + B2) * 0.5f;
            float e = Ap + 0.5f;                    // (C-D)/2 recovery term
            float t2s12 = (Cp - Dv) * 0.5f + e - t2m12;
            float ssum  = (Cp + Dv) * 0.5f + e - msum;
            float num = (t2m12 + C1) * (t2s12 + C2);
            float den = (msum + C1) * (ssum + C2) + 1e-8f;
            lsum += __fdividef(num, den);
        }
    }

    // ---- block reduce, unique partial slot ----
    #pragma unroll
    for (int o = 16; o; o >>= 1)
        lsum += __shfl_xor_sync(0xffffffffu, lsum, o);
    if ((tid & 31) == 0) red[tid >> 5] = lsum;
    __syncthreads();

    if (tid == 0) {
        float s = 0.f;
        #pragma unroll
        for (int w = 0; w < 16; w++) s += red[w];
        int bid = (blockIdx.z * GY + blockIdx.y) * GX + blockIdx.x;
        g_part[bid] = s;
        __threadfence();
        unsigned int prev = atomicAdd(&g_count, 1u);
        *lastflag = (prev == NBLK - 1) ? 1 : 0;
    }
    __syncthreads();

    // ---- last block: final reduction over all partials ----
    if (*lastflag) {
        __threadfence();
        const float4* p4 = (const float4*)g_part;
        float s = 0.f;
        #pragma unroll
        for (int it = 0; it < 3; it++) {
            float4 v = p4[tid + it * 512];
            s += (v.x + v.y) + (v.z + v.w);
        }
        #pragma unroll
        for (int o = 16; o; o >>= 1)
            s += __shfl_xor_sync(0xffffffffu, s, o);
        if ((tid & 31) == 0) red[tid >> 5] = s;
        __syncthreads();
        if (tid == 0) {
            float t = 0.f;
            #pragma unroll
            for (int w = 0; w < 16; w++) t += red[w];
            out[0] = (float)(1.0 - (double)t * (1.0 / N_PIX));
            g_count = 0;   // self-reset for next graph replay
        }
    }
}

extern "C" void kernel_launch(void* const* d_in, const int* in_sizes, int n_in,
                              void* d_out, int out_size)
{
    const float* pred = (const float*)d_in[0];
    const float* targ = (const float*)d_in[1];

    cudaFuncSetAttribute(ssim_tile_kernel,
                         cudaFuncAttributeMaxDynamicSharedMemorySize, SMEM_TOTAL);
    dim3 grid(GX, GY, N_PLANES);   // 16 x 4 x 96
    ssim_tile_kernel<<<grid, 512, SMEM_TOTAL>>>(pred, targ, (float*)d_out);
}